// round 2
// baseline (speedup 1.0000x reference)
#include <cuda_runtime.h>
#include <cuda_fp16.h>
#include <stdint.h>

#define N_LODS   6
#define TILE     128
#define THREADS  512
#define ASTRIDE  136   // act/weight smem row stride in halves (pad 128 -> 136 to kill ldmatrix bank conflicts)

// -------- device-global scratch (static allocation: allowed) --------
__device__ float  g_fm[5591040];        // interleaved [texel][16] fp32 features, gain folded in (22.4 MB)
__device__ __half g_w0[96 * 128];       // [k][n] fp16
__device__ __half g_w1[128 * 128];
__device__ __half g_w2[128 * 128];
__device__ __half g_w3[128 * 8];        // cols 3..7 zero-padded

__constant__ int c_loff[6] = {0, 256, 1280, 5376, 21760, 87296};  // texel offsets per LOD

// =====================================================================
// Prep kernel 1: [C,s,s] -> interleaved [texel][16] with gain 2^lg folded
// One thread per texel: 16 coalesced strided reads, 4x float4 coalesced writes.
// =====================================================================
__global__ void prep_fm(const float* __restrict__ f0, const float* __restrict__ f1,
                        const float* __restrict__ f2, const float* __restrict__ f3,
                        const float* __restrict__ f4, const float* __restrict__ f5,
                        const float* __restrict__ lg)
{
    int tex = blockIdx.x * blockDim.x + threadIdx.x;
    if (tex >= 349440) return;
    int lod; const float* f;
    if      (tex < 256)   { lod = 0; f = f0; }
    else if (tex < 1280)  { lod = 1; f = f1; }
    else if (tex < 5376)  { lod = 2; f = f2; }
    else if (tex < 21760) { lod = 3; f = f3; }
    else if (tex < 87296) { lod = 4; f = f4; }
    else                  { lod = 5; f = f5; }
    int local = tex - c_loff[lod];
    int ss = 1 << (2 * (4 + lod));          // s*s
    float gain = exp2f(lg[lod]);
    float v[16];
#pragma unroll
    for (int c = 0; c < 16; c++) v[c] = f[c * ss + local] * gain;
    float4* dst = reinterpret_cast<float4*>(g_fm) + tex * 4;
    dst[0] = make_float4(v[0],  v[1],  v[2],  v[3]);
    dst[1] = make_float4(v[4],  v[5],  v[6],  v[7]);
    dst[2] = make_float4(v[8],  v[9],  v[10], v[11]);
    dst[3] = make_float4(v[12], v[13], v[14], v[15]);
}

// =====================================================================
// Prep kernel 2: weights fp32 [out][in] -> fp16 [in][out] (k-major for mma B)
// =====================================================================
__global__ void prep_w(const float* __restrict__ w0, const float* __restrict__ w1,
                       const float* __restrict__ w2, const float* __restrict__ w3)
{
    int idx = blockIdx.x * blockDim.x + threadIdx.x;
    if (idx < 12288) {                       // w0: 96x128 (k x n)
        int n = idx & 127, k = idx >> 7;
        g_w0[idx] = __float2half(w0[n * 96 + k]);
    } else if (idx < 28672) {                // w1
        int i = idx - 12288;
        int n = i & 127, k = i >> 7;
        g_w1[i] = __float2half(w1[n * 128 + k]);
    } else if (idx < 45056) {                // w2
        int i = idx - 28672;
        int n = i & 127, k = i >> 7;
        g_w2[i] = __float2half(w2[n * 128 + k]);
    } else if (idx < 46080) {                // w3: 128x8, cols>=3 zero
        int i = idx - 45056;
        int n = i & 7, k = i >> 3;
        g_w3[i] = (n < 3) ? __float2half(w3[n * 128 + k]) : __float2half(0.f);
    }
}

// =====================================================================
// Main fused kernel
// =====================================================================
__device__ __forceinline__ uint32_t smem_u32(const void* p) {
    return (uint32_t)__cvta_generic_to_shared(p);
}

__device__ __forceinline__ void mma_16816(float* c, uint32_t a0, uint32_t a1, uint32_t a2, uint32_t a3,
                                          uint32_t b0, uint32_t b1) {
    asm volatile(
        "mma.sync.aligned.m16n8k16.row.col.f32.f16.f16.f32 "
        "{%0,%1,%2,%3},{%4,%5,%6,%7},{%8,%9},{%0,%1,%2,%3};\n"
        : "+f"(c[0]), "+f"(c[1]), "+f"(c[2]), "+f"(c[3])
        : "r"(a0), "r"(a1), "r"(a2), "r"(a3), "r"(b0), "r"(b1));
}

// One hidden layer: C[128pts x 128] = relu(A[128 x K] * W[K x 128] + b), written back to act (fp16).
// Warp tiling: warp = (m-tile 0..7, n-half 0..1); each warp: 16 rows x 64 cols.
template <int KT>
__device__ __forceinline__ void mlp_layer(__half* act, const __half* wsm, const float* bias,
                                          int mrow, int nb, int lane)
{
    float c[8][4];
    int cb = (lane & 3) * 2;
#pragma unroll
    for (int j = 0; j < 8; j++) {
        float b0v = bias[nb + j * 8 + cb];
        float b1v = bias[nb + j * 8 + cb + 1];
        c[j][0] = b0v; c[j][1] = b1v; c[j][2] = b0v; c[j][3] = b1v;
    }
    uint32_t abase = smem_u32(act + (mrow + (lane & 15)) * ASTRIDE + ((lane >> 4) << 3));
    uint32_t bbase = smem_u32(wsm + (lane & 15) * ASTRIDE + nb + ((lane >> 4) << 3));
#pragma unroll
    for (int kt = 0; kt < KT; kt++) {
        uint32_t a0, a1, a2, a3;
        asm volatile("ldmatrix.sync.aligned.m8n8.x4.shared.b16 {%0,%1,%2,%3}, [%4];\n"
                     : "=r"(a0), "=r"(a1), "=r"(a2), "=r"(a3)
                     : "r"(abase + kt * 32));
#pragma unroll
        for (int jj = 0; jj < 4; jj++) {
            uint32_t b0, b1, b2, b3;
            asm volatile("ldmatrix.sync.aligned.m8n8.x4.trans.shared.b16 {%0,%1,%2,%3}, [%4];\n"
                         : "=r"(b0), "=r"(b1), "=r"(b2), "=r"(b3)
                         : "r"(bbase + kt * (ASTRIDE * 2 * 16) + jj * 32));
            mma_16816(c[jj * 2 + 0], a0, a1, a2, a3, b0, b1);
            mma_16816(c[jj * 2 + 1], a0, a1, a2, a3, b2, b3);
        }
    }
    __syncthreads();   // everyone done reading act before we overwrite it
    int srow = mrow + (lane >> 2);
#pragma unroll
    for (int j = 0; j < 8; j++) {
        int col = nb + j * 8 + cb;
        __half2 h0 = __floats2half2_rn(fmaxf(c[j][0], 0.f), fmaxf(c[j][1], 0.f));
        __half2 h1 = __floats2half2_rn(fmaxf(c[j][2], 0.f), fmaxf(c[j][3], 0.f));
        *reinterpret_cast<__half2*>(act + srow * ASTRIDE + col)       = h0;
        *reinterpret_cast<__half2*>(act + (srow + 8) * ASTRIDE + col) = h1;
    }
    __syncthreads();
}

// Final layer 128 -> 3 (cols padded to 8, zero weights/bias beyond 3). Only n-half-0 warps run it.
__device__ __forceinline__ void mlp_out(const __half* act, const __half* w3s, const float* b3s,
                                        int mrow, int lane, float* __restrict__ out, int ptbase)
{
    float c[4];
    int cb = (lane & 3) * 2;
    c[0] = b3s[cb]; c[1] = b3s[cb + 1]; c[2] = c[0]; c[3] = c[1];
    uint32_t abase = smem_u32(act + (mrow + (lane & 15)) * ASTRIDE + ((lane >> 4) << 3));
    uint32_t bbase = smem_u32(w3s + (lane & 15) * 8);   // w3 row stride = 8 halves (16B)
#pragma unroll
    for (int kt = 0; kt < 8; kt++) {
        uint32_t a0, a1, a2, a3;
        asm volatile("ldmatrix.sync.aligned.m8n8.x4.shared.b16 {%0,%1,%2,%3}, [%4];\n"
                     : "=r"(a0), "=r"(a1), "=r"(a2), "=r"(a3)
                     : "r"(abase + kt * 32));
        uint32_t b0, b1;
        asm volatile("ldmatrix.sync.aligned.m8n8.x2.trans.shared.b16 {%0,%1}, [%2];\n"
                     : "=r"(b0), "=r"(b1)
                     : "r"(bbase + kt * 256));
        mma_16816(c, a0, a1, a2, a3, b0, b1);
    }
    int r = ptbase + mrow + (lane >> 2);
    if (cb == 0) {
        out[r * 3 + 0] = c[0];       out[r * 3 + 1] = c[1];
        out[(r + 8) * 3 + 0] = c[2]; out[(r + 8) * 3 + 1] = c[3];
    } else if (cb == 2) {
        out[r * 3 + 2] = c[0];
        out[(r + 8) * 3 + 2] = c[2];
    }
}

__global__ void __launch_bounds__(THREADS, 1) enc_main(
    const float2* __restrict__ coords,
    const float* __restrict__ b0, const float* __restrict__ b1,
    const float* __restrict__ b2, const float* __restrict__ b3,
    float* __restrict__ out, int ntiles)
{
    extern __shared__ __align__(16) char smem_raw[];
    __half* act = reinterpret_cast<__half*>(smem_raw);          // 128 x 136
    __half* w0s = act + TILE * ASTRIDE;                          // 96 x 136
    __half* w1s = w0s + 96 * ASTRIDE;                            // 128 x 136
    __half* w2s = w1s + 128 * ASTRIDE;                           // 128 x 136
    __half* w3s = w2s + 128 * ASTRIDE;                           // 128 x 8
    float*  bs  = reinterpret_cast<float*>(w3s + 128 * 8);       // 384 + 8 floats

    int tid = threadIdx.x;

    // Stage all weights + biases in smem once per block (persistent grid).
    {
        uint32_t*       d0 = (uint32_t*)w0s; const uint32_t* s0 = (const uint32_t*)g_w0;
        for (int i = tid; i < 96 * 64;  i += THREADS) d0[(i >> 6) * 68 + (i & 63)] = s0[i];
        uint32_t*       d1 = (uint32_t*)w1s; const uint32_t* s1 = (const uint32_t*)g_w1;
        for (int i = tid; i < 128 * 64; i += THREADS) d1[(i >> 6) * 68 + (i & 63)] = s1[i];
        uint32_t*       d2 = (uint32_t*)w2s; const uint32_t* s2 = (const uint32_t*)g_w2;
        for (int i = tid; i < 128 * 64; i += THREADS) d2[(i >> 6) * 68 + (i & 63)] = s2[i];
        uint32_t*       d3 = (uint32_t*)w3s; const uint32_t* s3 = (const uint32_t*)g_w3;
        for (int i = tid; i < 128 * 4;  i += THREADS) d3[i] = s3[i];
        for (int i = tid; i < 128; i += THREADS) {
            bs[i] = b0[i]; bs[128 + i] = b1[i]; bs[256 + i] = b2[i];
        }
        if (tid < 8) bs[384 + tid] = (tid < 3) ? b3[tid] : 0.f;
    }

    int warp = tid >> 5, lane = tid & 31;
    int mrow = (warp & 7) << 4;          // 8 m-tiles of 16 rows
    int nb   = (warp >> 3) << 6;         // 2 n-halves of 64 cols

    for (int tile = blockIdx.x; tile < ntiles; tile += gridDim.x) {
        __syncthreads();   // previous tile's readers of act done; also covers weight staging on iter 0

        // ---- gather: task = (pt, lod), 768 tasks over 512 threads ----
        for (int t = tid; t < TILE * N_LODS; t += THREADS) {
            int pt  = t & (TILE - 1);
            int lod = t >> 7;
            float2 g = coords[tile * TILE + pt];
            int sl = 4 + lod;
            int s  = 1 << sl;
            float sm1 = (float)(s - 1);
            float fx = fminf(fmaxf((g.x + 1.f) * 0.5f * sm1, 0.f), sm1);
            float fy = fminf(fmaxf((g.y + 1.f) * 0.5f * sm1, 0.f), sm1);
            float x0f = floorf(fx), y0f = floorf(fy);
            int   x0 = (int)x0f, y0 = (int)y0f;
            float wx = fx - x0f, wy = fy - y0f;
            int   x1 = min(x0 + 1, s - 1);
            int   y1 = min(y0 + 1, s - 1);
            const float4* base = reinterpret_cast<const float4*>(g_fm) + (c_loff[lod] << 2);
            const float4* p00 = base + (((y0 << sl) + x0) << 2);
            const float4* p10 = base + (((y0 << sl) + x1) << 2);
            const float4* p01 = base + (((y1 << sl) + x0) << 2);
            const float4* p11 = base + (((y1 << sl) + x1) << 2);
            float w00 = (1.f - wx) * (1.f - wy), w10 = wx * (1.f - wy);
            float w01 = (1.f - wx) * wy,         w11 = wx * wy;
            __half2* dst = reinterpret_cast<__half2*>(act + pt * ASTRIDE + lod * 16);
#pragma unroll
            for (int cq = 0; cq < 4; cq++) {
                float4 a = p00[cq], bb = p10[cq], cc = p01[cq], dd = p11[cq];
                float r0 = a.x * w00 + bb.x * w10 + cc.x * w01 + dd.x * w11;
                float r1 = a.y * w00 + bb.y * w10 + cc.y * w01 + dd.y * w11;
                float r2 = a.z * w00 + bb.z * w10 + cc.z * w01 + dd.z * w11;
                float r3 = a.w * w00 + bb.w * w10 + cc.w * w01 + dd.w * w11;
                dst[cq * 2 + 0] = __floats2half2_rn(r0, r1);
                dst[cq * 2 + 1] = __floats2half2_rn(r2, r3);
            }
        }
        __syncthreads();

        // ---- MLP on tensor cores ----
        mlp_layer<6>(act, w0s, bs,       mrow, nb, lane);   // 96 -> 128
        mlp_layer<8>(act, w1s, bs + 128, mrow, nb, lane);   // 128 -> 128
        mlp_layer<8>(act, w2s, bs + 256, mrow, nb, lane);   // 128 -> 128
        if (nb == 0) mlp_out(act, w3s, bs + 384, mrow, lane, out, tile * TILE);  // 128 -> 3
    }
}

// =====================================================================
extern "C" void kernel_launch(void* const* d_in, const int* in_sizes, int n_in,
                              void* d_out, int out_size)
{
    const float* xc = (const float*)d_in[0];
    const float* f0 = (const float*)d_in[1];
    const float* f1 = (const float*)d_in[2];
    const float* f2 = (const float*)d_in[3];
    const float* f3 = (const float*)d_in[4];
    const float* f4 = (const float*)d_in[5];
    const float* f5 = (const float*)d_in[6];
    const float* lg = (const float*)d_in[7];
    const float* w0 = (const float*)d_in[8];
    const float* b0 = (const float*)d_in[9];
    const float* w1 = (const float*)d_in[10];
    const float* b1 = (const float*)d_in[11];
    const float* w2 = (const float*)d_in[12];
    const float* b2 = (const float*)d_in[13];
    const float* w3 = (const float*)d_in[14];
    const float* b3 = (const float*)d_in[15];

    int npts   = in_sizes[0] / 2;          // (1,H,W,2) -> H*W points
    int ntiles = npts / TILE;              // 8192 for 1024x1024

    prep_fm<<<(349440 + 255) / 256, 256>>>(f0, f1, f2, f3, f4, f5, lg);
    prep_w<<<(46080 + 255) / 256, 256>>>(w0, w1, w2, w3);

    constexpr int SMEM_BYTES =
        (TILE * ASTRIDE + 96 * ASTRIDE + 2 * 128 * ASTRIDE + 128 * 8) * 2 + 392 * 4;  // 134,176 B

    cudaFuncSetAttribute(enc_main, cudaFuncAttributeMaxDynamicSharedMemorySize, SMEM_BYTES);
    int nsm = 0;
    cudaDeviceGetAttribute(&nsm, cudaDevAttrMultiProcessorCount, 0);
    if (nsm <= 0) nsm = 148;

    enc_main<<<nsm, THREADS, SMEM_BYTES>>>(
        (const float2*)xc, b0, b1, b2, b3, (float*)d_out, ntiles);
}

// round 3
// speedup vs baseline: 1.2452x; 1.2452x over previous
#include <cuda_runtime.h>
#include <cuda_fp16.h>
#include <stdint.h>

#define N_LODS   6
#define TILE     64
#define THREADS  256
#define ASTRIDE  136   // act smem row stride in halves (16B-aligned rows, conflict-free ldmatrix)

// -------- device-global scratch (static allocation: allowed) --------
__device__ __half g_fm[349440 * 16];    // interleaved [texel][16] fp16 features, gain folded (11.2 MB)
__device__ __half g_w0[96 * 128];       // [k][n] fp16, 16B-chunk XOR-swizzled
__device__ __half g_w1[128 * 128];
__device__ __half g_w2[128 * 128];
__device__ __half g_w3[128 * 8];        // linear, cols 3..7 zero-padded

__constant__ int c_loff[6] = {0, 256, 1280, 5376, 21760, 87296};  // texel offsets per LOD

// swizzled offset for [k][n] weight, 128 cols: 16B chunk index XORed with (k&7)
__device__ __forceinline__ int wswz(int k, int n) {
    return k * 128 + ((((n >> 3) ^ (k & 7))) << 3) + (n & 7);
}

// =====================================================================
// Merged prep kernel: feature-map interleave (fp16) + weight transpose/swizzle
// =====================================================================
__global__ void prep_all(const float* __restrict__ f0, const float* __restrict__ f1,
                         const float* __restrict__ f2, const float* __restrict__ f3,
                         const float* __restrict__ f4, const float* __restrict__ f5,
                         const float* __restrict__ lg,
                         const float* __restrict__ w0, const float* __restrict__ w1,
                         const float* __restrict__ w2, const float* __restrict__ w3)
{
    int idx = blockIdx.x * blockDim.x + threadIdx.x;
    if (idx < 349440) {
        int tex = idx;
        int lod; const float* f;
        if      (tex < 256)   { lod = 0; f = f0; }
        else if (tex < 1280)  { lod = 1; f = f1; }
        else if (tex < 5376)  { lod = 2; f = f2; }
        else if (tex < 21760) { lod = 3; f = f3; }
        else if (tex < 87296) { lod = 4; f = f4; }
        else                  { lod = 5; f = f5; }
        int local = tex - c_loff[lod];
        int ss = 1 << (2 * (4 + lod));
        float gain = exp2f(lg[lod]);
        __half h[16];
#pragma unroll
        for (int c = 0; c < 16; c++) h[c] = __float2half(f[c * ss + local] * gain);
        uint4* dst = reinterpret_cast<uint4*>(g_fm + tex * 16);
        dst[0] = *reinterpret_cast<uint4*>(&h[0]);
        dst[1] = *reinterpret_cast<uint4*>(&h[8]);
        return;
    }
    int i = idx - 349440;
    if (i < 12288) {                         // w0: 96x128 (k x n)
        int n = i & 127, k = i >> 7;
        g_w0[wswz(k, n)] = __float2half(w0[n * 96 + k]);
    } else if (i < 28672) {                  // w1
        int j = i - 12288;
        int n = j & 127, k = j >> 7;
        g_w1[wswz(k, n)] = __float2half(w1[n * 128 + k]);
    } else if (i < 45056) {                  // w2
        int j = i - 28672;
        int n = j & 127, k = j >> 7;
        g_w2[wswz(k, n)] = __float2half(w2[n * 128 + k]);
    } else if (i < 46080) {                  // w3: 128x8, linear, n>=3 zero
        int j = i - 45056;
        int n = j & 7, k = j >> 3;
        g_w3[j] = (n < 3) ? __float2half(w3[n * 128 + k]) : __float2half(0.f);
    }
}

// =====================================================================
// Main fused kernel
// =====================================================================
__device__ __forceinline__ uint32_t smem_u32(const void* p) {
    return (uint32_t)__cvta_generic_to_shared(p);
}

__device__ __forceinline__ void mma_16816(float* c, uint32_t a0, uint32_t a1, uint32_t a2, uint32_t a3,
                                          uint32_t b0, uint32_t b1) {
    asm volatile(
        "mma.sync.aligned.m16n8k16.row.col.f32.f16.f16.f32 "
        "{%0,%1,%2,%3},{%4,%5,%6,%7},{%8,%9},{%0,%1,%2,%3};\n"
        : "+f"(c[0]), "+f"(c[1]), "+f"(c[2]), "+f"(c[3])
        : "r"(a0), "r"(a1), "r"(a2), "r"(a3), "r"(b0), "r"(b1));
}

// One hidden layer: C[64pts x 128] = relu(A[64 x K] * W[K x 128] + b), written back to act (fp16).
// 8 warps: warp = (m-tile 0..3, n-half 0..1); each warp: 16 rows x 64 cols.
// Weights in smem are [k][128] with 16B-chunk XOR swizzle (chunk ^ (k&7)).
template <int KT>
__device__ __forceinline__ void mlp_layer(__half* act, const __half* wsm, const float* bias,
                                          int mrow, int nb, int lane)
{
    float c[8][4];
    int cb = (lane & 3) * 2;
#pragma unroll
    for (int j = 0; j < 8; j++) {
        float b0v = bias[nb + j * 8 + cb];
        float b1v = bias[nb + j * 8 + cb + 1];
        c[j][0] = b0v; c[j][1] = b1v; c[j][2] = b0v; c[j][3] = b1v;
    }
    uint32_t abase = smem_u32(act + (mrow + (lane & 15)) * ASTRIDE) + ((lane >> 4) << 4);
    uint32_t wbase = smem_u32(wsm) + ((lane & 15) << 8);   // k-row * 256B
    int chunk0 = (nb >> 3) + (lane >> 4);
    int xorv = lane & 7;
#pragma unroll
    for (int kt = 0; kt < KT; kt++) {
        uint32_t a0, a1, a2, a3;
        asm volatile("ldmatrix.sync.aligned.m8n8.x4.shared.b16 {%0,%1,%2,%3}, [%4];\n"
                     : "=r"(a0), "=r"(a1), "=r"(a2), "=r"(a3)
                     : "r"(abase + kt * 32));
#pragma unroll
        for (int jj = 0; jj < 4; jj++) {
            uint32_t baddr = wbase + (kt << 12) + ((uint32_t)(((chunk0 + jj * 2) ^ xorv)) << 4);
            uint32_t b0, b1, b2, b3;
            asm volatile("ldmatrix.sync.aligned.m8n8.x4.trans.shared.b16 {%0,%1,%2,%3}, [%4];\n"
                         : "=r"(b0), "=r"(b1), "=r"(b2), "=r"(b3)
                         : "r"(baddr));
            mma_16816(c[jj * 2 + 0], a0, a1, a2, a3, b0, b1);
            mma_16816(c[jj * 2 + 1], a0, a1, a2, a3, b2, b3);
        }
    }
    __syncthreads();   // everyone done reading act before overwrite
    int srow = mrow + (lane >> 2);
#pragma unroll
    for (int j = 0; j < 8; j++) {
        int col = nb + j * 8 + cb;
        __half2 h0 = __floats2half2_rn(fmaxf(c[j][0], 0.f), fmaxf(c[j][1], 0.f));
        __half2 h1 = __floats2half2_rn(fmaxf(c[j][2], 0.f), fmaxf(c[j][3], 0.f));
        *reinterpret_cast<__half2*>(act + srow * ASTRIDE + col)       = h0;
        *reinterpret_cast<__half2*>(act + (srow + 8) * ASTRIDE + col) = h1;
    }
    __syncthreads();
}

// Final layer 128 -> 3 (cols padded to 8). Only n-half-0 warps (0..3) run it.
__device__ __forceinline__ void mlp_out(const __half* act, const __half* w3s, const float* b3s,
                                        int mrow, int lane, float* __restrict__ out, int ptbase)
{
    float c[4];
    int cb = (lane & 3) * 2;
    c[0] = b3s[cb]; c[1] = b3s[cb + 1]; c[2] = c[0]; c[3] = c[1];
    uint32_t abase = smem_u32(act + (mrow + (lane & 15)) * ASTRIDE) + ((lane >> 4) << 4);
    uint32_t bbase = smem_u32(w3s) + ((lane & 15) << 4);   // w3 row stride = 16B
#pragma unroll
    for (int kt = 0; kt < 8; kt++) {
        uint32_t a0, a1, a2, a3;
        asm volatile("ldmatrix.sync.aligned.m8n8.x4.shared.b16 {%0,%1,%2,%3}, [%4];\n"
                     : "=r"(a0), "=r"(a1), "=r"(a2), "=r"(a3)
                     : "r"(abase + kt * 32));
        uint32_t b0, b1;
        asm volatile("ldmatrix.sync.aligned.m8n8.x2.trans.shared.b16 {%0,%1}, [%2];\n"
                     : "=r"(b0), "=r"(b1)
                     : "r"(bbase + kt * 256));
        mma_16816(c, a0, a1, a2, a3, b0, b1);
    }
    int r = ptbase + mrow + (lane >> 2);
    if (cb == 0) {
        out[r * 3 + 0] = c[0];       out[r * 3 + 1] = c[1];
        out[(r + 8) * 3 + 0] = c[2]; out[(r + 8) * 3 + 1] = c[3];
    } else if (cb == 2) {
        out[r * 3 + 2] = c[0];
        out[(r + 8) * 3 + 2] = c[2];
    }
}

__global__ void __launch_bounds__(THREADS, 2) enc_main(
    const float2* __restrict__ coords,
    const float* __restrict__ b0, const float* __restrict__ b1,
    const float* __restrict__ b2, const float* __restrict__ b3,
    float* __restrict__ out, int ntiles)
{
    extern __shared__ __align__(16) char smem_raw[];
    __half* act = reinterpret_cast<__half*>(smem_raw);           // 64 x 136
    __half* w0s = act + TILE * ASTRIDE;                           // 96 x 128 (swizzled)
    __half* w1s = w0s + 96 * 128;                                 // 128 x 128 (swizzled)
    __half* w2s = w1s + 128 * 128;                                // 128 x 128 (swizzled)
    __half* w3s = w2s + 128 * 128;                                // 128 x 8 (linear)
    float*  bs  = reinterpret_cast<float*>(w3s + 128 * 8);        // 384 + 8 floats

    int tid = threadIdx.x;

    // Stage weights + biases in smem once per block (persistent grid). Straight copies.
    {
        uint4* dw = (uint4*)w0s;              // w0s..w3s contiguous: (12288+16384+16384+1024)/8 uint4
        const uint4* s0 = (const uint4*)g_w0;
        for (int i = tid; i < 12288 / 8; i += THREADS) dw[i] = s0[i];
        const uint4* s1 = (const uint4*)g_w1;
        for (int i = tid; i < 16384 / 8; i += THREADS) dw[1536 + i] = s1[i];
        const uint4* s2 = (const uint4*)g_w2;
        for (int i = tid; i < 16384 / 8; i += THREADS) dw[3584 + i] = s2[i];
        const uint4* s3 = (const uint4*)g_w3;
        for (int i = tid; i < 1024 / 8;  i += THREADS) dw[5632 + i] = s3[i];
        for (int i = tid; i < 128; i += THREADS) {
            bs[i] = b0[i]; bs[128 + i] = b1[i]; bs[256 + i] = b2[i];
        }
        if (tid < 8) bs[384 + tid] = (tid < 3) ? b3[tid] : 0.f;
    }

    int warp = tid >> 5, lane = tid & 31;
    int mrow = (warp & 3) << 4;          // 4 m-tiles of 16 rows
    int nb   = (warp >> 2) << 6;         // 2 n-halves of 64 cols

    for (int tile = blockIdx.x; tile < ntiles; tile += gridDim.x) {
        __syncthreads();   // prev tile's act readers done; also covers weight staging on iter 0

        // ---- gather: subtask = (pt, lod, half16B), 768 subtasks over 256 threads, 3 even iters ----
#pragma unroll
        for (int it = 0; it < 3; it++) {
            int t   = tid + it * THREADS;
            int pt  = t & (TILE - 1);
            int rest = t >> 6;              // 0..11
            int lod = rest >> 1;
            int hf  = rest & 1;
            float2 g = coords[tile * TILE + pt];
            int sl = 4 + lod;
            int s  = 1 << sl;
            float sm1 = (float)(s - 1);
            float fx = fminf(fmaxf((g.x + 1.f) * 0.5f * sm1, 0.f), sm1);
            float fy = fminf(fmaxf((g.y + 1.f) * 0.5f * sm1, 0.f), sm1);
            float x0f = floorf(fx), y0f = floorf(fy);
            int   x0 = (int)x0f, y0 = (int)y0f;
            float wx = fx - x0f, wy = fy - y0f;
            int   x1 = min(x0 + 1, s - 1);
            int   y1 = min(y0 + 1, s - 1);
            // texel -> 16 halves = 2 uint4; hf selects which 8-half group
            const uint4* base = reinterpret_cast<const uint4*>(g_fm) + ((c_loff[lod]) << 1) + hf;
            uint4 t00 = base[(((y0 << sl) + x0) << 1)];
            uint4 t10 = base[(((y0 << sl) + x1) << 1)];
            uint4 t01 = base[(((y1 << sl) + x0) << 1)];
            uint4 t11 = base[(((y1 << sl) + x1) << 1)];
            float w00 = (1.f - wx) * (1.f - wy), w10 = wx * (1.f - wy);
            float w01 = (1.f - wx) * wy,         w11 = wx * wy;
            const __half2* h00 = reinterpret_cast<const __half2*>(&t00);
            const __half2* h10 = reinterpret_cast<const __half2*>(&t10);
            const __half2* h01 = reinterpret_cast<const __half2*>(&t01);
            const __half2* h11 = reinterpret_cast<const __half2*>(&t11);
            uint4 res;
            __half2* ro = reinterpret_cast<__half2*>(&res);
#pragma unroll
            for (int e = 0; e < 4; e++) {
                float2 a = __half22float2(h00[e]);
                float2 b = __half22float2(h10[e]);
                float2 c = __half22float2(h01[e]);
                float2 d = __half22float2(h11[e]);
                float rx = a.x * w00 + b.x * w10 + c.x * w01 + d.x * w11;
                float ry = a.y * w00 + b.y * w10 + c.y * w01 + d.y * w11;
                ro[e] = __floats2half2_rn(rx, ry);
            }
            *reinterpret_cast<uint4*>(act + pt * ASTRIDE + lod * 16 + hf * 8) = res;
        }
        __syncthreads();

        // ---- MLP on tensor cores ----
        mlp_layer<6>(act, w0s, bs,       mrow, nb, lane);   // 96 -> 128
        mlp_layer<8>(act, w1s, bs + 128, mrow, nb, lane);   // 128 -> 128
        mlp_layer<8>(act, w2s, bs + 256, mrow, nb, lane);   // 128 -> 128
        if (nb == 0) mlp_out(act, w3s, bs + 384, mrow, lane, out, tile * TILE);  // 128 -> 3
    }
}

// =====================================================================
extern "C" void kernel_launch(void* const* d_in, const int* in_sizes, int n_in,
                              void* d_out, int out_size)
{
    const float* xc = (const float*)d_in[0];
    const float* f0 = (const float*)d_in[1];
    const float* f1 = (const float*)d_in[2];
    const float* f2 = (const float*)d_in[3];
    const float* f3 = (const float*)d_in[4];
    const float* f4 = (const float*)d_in[5];
    const float* f5 = (const float*)d_in[6];
    const float* lg = (const float*)d_in[7];
    const float* w0 = (const float*)d_in[8];
    const float* b0 = (const float*)d_in[9];
    const float* w1 = (const float*)d_in[10];
    const float* b1 = (const float*)d_in[11];
    const float* w2 = (const float*)d_in[12];
    const float* b2 = (const float*)d_in[13];
    const float* w3 = (const float*)d_in[14];
    const float* b3 = (const float*)d_in[15];

    int npts   = in_sizes[0] / 2;
    int ntiles = npts / TILE;              // 16384 for 1024x1024

    prep_all<<<(349440 + 46080 + 255) / 256, 256>>>(f0, f1, f2, f3, f4, f5, lg, w0, w1, w2, w3);

    constexpr int SMEM_BYTES =
        (TILE * ASTRIDE + 96 * 128 + 2 * 128 * 128 + 128 * 8) * 2 + 392 * 4;  // 111,136 B

    cudaFuncSetAttribute(enc_main, cudaFuncAttributeMaxDynamicSharedMemorySize, SMEM_BYTES);
    int nsm = 0;
    cudaDeviceGetAttribute(&nsm, cudaDevAttrMultiProcessorCount, 0);
    if (nsm <= 0) nsm = 148;

    enc_main<<<2 * nsm, THREADS, SMEM_BYTES>>>(
        (const float2*)xc, b0, b1, b2, b3, (float*)d_out, ntiles);
}

// round 6
// speedup vs baseline: 1.7828x; 1.4318x over previous
#include <cuda_runtime.h>
#include <cuda_fp16.h>
#include <stdint.h>

#define THREADS  384
#define TILE     128
#define A0STRIDE 104   // act0 row stride in halves (208B = 13*16B, conflict-free)
#define ASTRIDE  136   // act row stride in halves (272B = 17*16B, conflict-free)

// -------- device-global scratch --------
__device__ __half g_fm[349440 * 16];    // interleaved [texel][16] fp16, gain folded (11.2 MB)
__device__ __half g_w0[96 * 128];       // [k][n] fp16, 16B-chunk XOR-swizzled
__device__ __half g_w1[128 * 128];
__device__ __half g_w2[128 * 128];
__device__ __half g_w3[128 * 8];        // linear, cols 3..7 zero-padded

__constant__ int c_loff[6] = {0, 256, 1280, 5376, 21760, 87296};

// swizzled offset for [k][n] weight, 128 cols: 16B chunk index XORed with (k&7)
__device__ __forceinline__ int wswz(int k, int n) {
    return k * 128 + ((((n >> 3) ^ (k & 7))) << 3) + (n & 7);
}

// =====================================================================
// Prep kernel: fm interleave (fp16) + weight transpose/swizzle
// =====================================================================
__global__ void prep_all(const float* __restrict__ f0, const float* __restrict__ f1,
                         const float* __restrict__ f2, const float* __restrict__ f3,
                         const float* __restrict__ f4, const float* __restrict__ f5,
                         const float* __restrict__ lg,
                         const float* __restrict__ w0, const float* __restrict__ w1,
                         const float* __restrict__ w2, const float* __restrict__ w3)
{
    int idx = blockIdx.x * blockDim.x + threadIdx.x;
    if (idx < 349440) {
        int tex = idx;
        int lod; const float* f;
        if      (tex < 256)   { lod = 0; f = f0; }
        else if (tex < 1280)  { lod = 1; f = f1; }
        else if (tex < 5376)  { lod = 2; f = f2; }
        else if (tex < 21760) { lod = 3; f = f3; }
        else if (tex < 87296) { lod = 4; f = f4; }
        else                  { lod = 5; f = f5; }
        int local = tex - c_loff[lod];
        int ss = 1 << (2 * (4 + lod));
        float gain = exp2f(lg[lod]);
        __half h[16];
#pragma unroll
        for (int c = 0; c < 16; c++) h[c] = __float2half(f[c * ss + local] * gain);
        uint4* dst = reinterpret_cast<uint4*>(g_fm + tex * 16);
        dst[0] = *reinterpret_cast<uint4*>(&h[0]);
        dst[1] = *reinterpret_cast<uint4*>(&h[8]);
        return;
    }
    int i = idx - 349440;
    if (i < 12288) {                         // w0: 96x128 (k x n)
        int n = i & 127, k = i >> 7;
        g_w0[wswz(k, n)] = __float2half(w0[n * 96 + k]);
    } else if (i < 28672) {                  // w1
        int j = i - 12288;
        int n = j & 127, k = j >> 7;
        g_w1[wswz(k, n)] = __float2half(w1[n * 128 + k]);
    } else if (i < 45056) {                  // w2
        int j = i - 28672;
        int n = j & 127, k = j >> 7;
        g_w2[wswz(k, n)] = __float2half(w2[n * 128 + k]);
    } else if (i < 46080) {                  // w3: 128x8, linear, n>=3 zero
        int j = i - 45056;
        int n = j & 7, k = j >> 3;
        g_w3[j] = (n < 3) ? __float2half(w3[n * 128 + k]) : __float2half(0.f);
    }
}

// =====================================================================
__device__ __forceinline__ uint32_t smem_u32(const void* p) {
    return (uint32_t)__cvta_generic_to_shared(p);
}

__device__ __forceinline__ void mma_16816(float* c, uint32_t a0, uint32_t a1, uint32_t a2, uint32_t a3,
                                          uint32_t b0, uint32_t b1) {
    asm volatile(
        "mma.sync.aligned.m16n8k16.row.col.f32.f16.f16.f32 "
        "{%0,%1,%2,%3},{%4,%5,%6,%7},{%8,%9},{%0,%1,%2,%3};\n"
        : "+f"(c[0]), "+f"(c[1]), "+f"(c[2]), "+f"(c[3])
        : "r"(a0), "r"(a1), "r"(a2), "r"(a3), "r"(b0), "r"(b1));
}

// One hidden layer. 8 MLP warps: warp = (mq 0..1 [64 rows], nq 0..3 [32 cols]).
// Per warp: C = 16 mma frags (m64 x n32), B reloaded once per kt (shared across 4 m-chunks).
// Internal barriers use named barrier 1 with 256 threads (the MLP warps only).
template <int KT, int INSTRIDE>
__device__ __forceinline__ void mlp_layer(const __half* ain, const __half* wsm, const float* bias,
                                          int mq, int nq, int lane, __half* aout)
{
    float c[16][4];
    int cb = (lane & 3) * 2;
#pragma unroll
    for (int mi = 0; mi < 4; mi++)
#pragma unroll
        for (int nj = 0; nj < 4; nj++) {
            float b0v = bias[nq * 32 + nj * 8 + cb];
            float b1v = bias[nq * 32 + nj * 8 + cb + 1];
            float* cc = c[mi * 4 + nj];
            cc[0] = b0v; cc[1] = b1v; cc[2] = b0v; cc[3] = b1v;
        }
    uint32_t abase = smem_u32(ain + (mq * 64 + (lane & 15)) * INSTRIDE) + ((lane >> 4) << 4);
    uint32_t wbase = smem_u32(wsm) + ((lane & 15) << 8);   // k-row * 256B
    int chunk0 = nq * 4 + (lane >> 4);
    int xorv = lane & 7;
#pragma unroll
    for (int kt = 0; kt < KT; kt++) {
        uint32_t b[8];
#pragma unroll
        for (int jj = 0; jj < 2; jj++) {
            uint32_t baddr = wbase + (kt << 12) + ((uint32_t)((chunk0 + jj * 2) ^ xorv) << 4);
            asm volatile("ldmatrix.sync.aligned.m8n8.x4.trans.shared.b16 {%0,%1,%2,%3}, [%4];\n"
                         : "=r"(b[jj * 4 + 0]), "=r"(b[jj * 4 + 1]), "=r"(b[jj * 4 + 2]), "=r"(b[jj * 4 + 3])
                         : "r"(baddr));
        }
#pragma unroll
        for (int mi = 0; mi < 4; mi++) {
            uint32_t a0, a1, a2, a3;
            asm volatile("ldmatrix.sync.aligned.m8n8.x4.shared.b16 {%0,%1,%2,%3}, [%4];\n"
                         : "=r"(a0), "=r"(a1), "=r"(a2), "=r"(a3)
                         : "r"(abase + mi * (16 * INSTRIDE * 2) + kt * 32));
            mma_16816(c[mi * 4 + 0], a0, a1, a2, a3, b[0], b[1]);
            mma_16816(c[mi * 4 + 1], a0, a1, a2, a3, b[2], b[3]);
            mma_16816(c[mi * 4 + 2], a0, a1, a2, a3, b[4], b[5]);
            mma_16816(c[mi * 4 + 3], a0, a1, a2, a3, b[6], b[7]);
        }
    }
    asm volatile("bar.sync 1, 256;" ::: "memory");   // all act/prev-layer reads done
#pragma unroll
    for (int mi = 0; mi < 4; mi++) {
        int srow = mq * 64 + mi * 16 + (lane >> 2);
#pragma unroll
        for (int nj = 0; nj < 4; nj++) {
            int col = nq * 32 + nj * 8 + cb;
            float* cc = c[mi * 4 + nj];
            __half2 h0 = __floats2half2_rn(fmaxf(cc[0], 0.f), fmaxf(cc[1], 0.f));
            __half2 h1 = __floats2half2_rn(fmaxf(cc[2], 0.f), fmaxf(cc[3], 0.f));
            *reinterpret_cast<__half2*>(aout + srow * ASTRIDE + col)       = h0;
            *reinterpret_cast<__half2*>(aout + (srow + 8) * ASTRIDE + col) = h1;
        }
    }
    asm volatile("bar.sync 1, 256;" ::: "memory");   // writes visible before next layer reads
}

// Final layer 128 -> 3 (padded 8). Only nq==0 warps (wid 0 and 4) call this; each handles m=64.
__device__ __forceinline__ void mlp_out(const __half* act, const __half* w3s, const float* b3s,
                                        int mq, int lane, float* __restrict__ out, int ptbase)
{
    float c[4][4];
    int cb = (lane & 3) * 2;
#pragma unroll
    for (int mi = 0; mi < 4; mi++) {
        c[mi][0] = b3s[cb]; c[mi][1] = b3s[cb + 1]; c[mi][2] = c[mi][0]; c[mi][3] = c[mi][1];
    }
    uint32_t abase = smem_u32(act + (mq * 64 + (lane & 15)) * ASTRIDE) + ((lane >> 4) << 4);
    uint32_t bbase = smem_u32(w3s) + ((lane & 15) << 4);   // w3 row stride = 16B
#pragma unroll
    for (int kt = 0; kt < 8; kt++) {
        uint32_t b0, b1;
        asm volatile("ldmatrix.sync.aligned.m8n8.x2.trans.shared.b16 {%0,%1}, [%2];\n"
                     : "=r"(b0), "=r"(b1) : "r"(bbase + kt * 256));
#pragma unroll
        for (int mi = 0; mi < 4; mi++) {
            uint32_t a0, a1, a2, a3;
            asm volatile("ldmatrix.sync.aligned.m8n8.x4.shared.b16 {%0,%1,%2,%3}, [%4];\n"
                         : "=r"(a0), "=r"(a1), "=r"(a2), "=r"(a3)
                         : "r"(abase + mi * (16 * ASTRIDE * 2) + kt * 32));
            mma_16816(c[mi], a0, a1, a2, a3, b0, b1);
        }
    }
#pragma unroll
    for (int mi = 0; mi < 4; mi++) {
        int r = ptbase + mq * 64 + mi * 16 + (lane >> 2);
        if (cb == 0) {
            out[r * 3 + 0] = c[mi][0];       out[r * 3 + 1] = c[mi][1];
            out[(r + 8) * 3 + 0] = c[mi][2]; out[(r + 8) * 3 + 1] = c[mi][3];
        } else if (cb == 2) {
            out[r * 3 + 2] = c[mi][0];
            out[(r + 8) * 3 + 2] = c[mi][2];
        }
    }
}

// ---------------- SMEM layout (bytes) ----------------
#define S_ACT0  0                       // 2 x 128 x 104 halves = 53248 B
#define S_ACT   53248                   // 128 x 136 halves = 34816 B
#define S_W     88064                   // 46080 halves = 92160 B (w0|w1|w2|w3 contiguous)
#define S_BIAS  180224                  // 392 floats
#define SMEM_BYTES (180224 + 1600)

// =====================================================================
__global__ void __launch_bounds__(THREADS, 1) enc_main(
    const float2* __restrict__ coords,
    const float* __restrict__ b0, const float* __restrict__ b1,
    const float* __restrict__ b2, const float* __restrict__ b3,
    float* __restrict__ out, int ntiles)
{
    extern __shared__ __align__(16) char sm[];
    __half* act0 = reinterpret_cast<__half*>(sm + S_ACT0);   // [2][128][104]
    __half* act  = reinterpret_cast<__half*>(sm + S_ACT);    // [128][136]
    __half* w0s  = reinterpret_cast<__half*>(sm + S_W);
    __half* w1s  = w0s + 12288;
    __half* w2s  = w1s + 16384;
    __half* w3s  = w2s + 16384;
    float*  bs   = reinterpret_cast<float*>(sm + S_BIAS);

    int tid = threadIdx.x;

    // ---- stage weights + biases (straight copies; global layout == smem layout) ----
    {
        uint4* dw = (uint4*)w0s;
        const uint4* s0 = (const uint4*)g_w0;
        for (int i = tid; i < 12288 / 8; i += THREADS) dw[i] = s0[i];
        const uint4* s1 = (const uint4*)g_w1;
        for (int i = tid; i < 16384 / 8; i += THREADS) dw[1536 + i] = s1[i];
        const uint4* s2 = (const uint4*)g_w2;
        for (int i = tid; i < 16384 / 8; i += THREADS) dw[3584 + i] = s2[i];
        const uint4* s3 = (const uint4*)g_w3;
        for (int i = tid; i < 1024 / 8;  i += THREADS) dw[5632 + i] = s3[i];
        for (int i = tid; i < 128; i += THREADS) {
            bs[i] = b0[i]; bs[128 + i] = b1[i]; bs[256 + i] = b2[i];
        }
        if (tid < 8) bs[384 + tid] = (tid < 3) ? b3[tid] : 0.f;
    }
    __syncthreads();

    int wid = tid >> 5, lane = tid & 31;

    if (wid < 8) {
        // ================= MLP warps (256 threads) =================
        int mq = wid >> 2;          // 0,1 -> rows [mq*64, +64)
        int nq = wid & 3;           // 0..3 -> cols [nq*32, +32)
        int li = 0;
        for (int tile = blockIdx.x; tile < ntiles; tile += gridDim.x, li++) {
            int buf = li & 1;
            // wait for gather to fill act0[buf]
            asm volatile("bar.sync %0, 384;" :: "r"(2 + buf) : "memory");
            const __half* a0 = act0 + buf * (128 * A0STRIDE);

            mlp_layer<6, A0STRIDE>(a0, w0s, bs, mq, nq, lane, act);        // 96 -> 128
            // act0[buf] fully consumed -> release to gather
            asm volatile("bar.arrive %0, 384;" :: "r"(4 + buf) : "memory");
            mlp_layer<8, ASTRIDE>(act, w1s, bs + 128, mq, nq, lane, act);  // 128 -> 128
            mlp_layer<8, ASTRIDE>(act, w2s, bs + 256, mq, nq, lane, act);  // 128 -> 128
            if (nq == 0) mlp_out(act, w3s, bs + 384, mq, lane, out, tile * TILE);
            // next tile's L0 write to act is gated by the bar.sync(1,256) inside mlp_layer,
            // which the out-warps reach only after their reads complete.
        }
    } else {
        // ================= gather warps (128 threads) =================
        int ptid = tid - 256;       // 0..127 point row
        int li = 0;
        for (int tile = blockIdx.x; tile < ntiles; tile += gridDim.x, li++) {
            int buf = li & 1;
            if (li >= 2)
                asm volatile("bar.sync %0, 384;" :: "r"(4 + buf) : "memory");
            __half* a0 = act0 + buf * (128 * A0STRIDE);

            float2 g = coords[tile * TILE + ptid];
            float gx = (g.x + 1.f) * 0.5f;
            float gy = (g.y + 1.f) * 0.5f;
#pragma unroll
            for (int lod = 0; lod < 6; lod++) {
                const int sl = 4 + lod;
                const int s  = 1 << sl;
                const float sm1 = (float)(s - 1);
                float fx = fminf(fmaxf(gx * sm1, 0.f), sm1);
                float fy = fminf(fmaxf(gy * sm1, 0.f), sm1);
                float x0f = floorf(fx), y0f = floorf(fy);
                int   x0 = (int)x0f, y0 = (int)y0f;
                float wx = fx - x0f, wy = fy - y0f;
                int   x1 = min(x0 + 1, s - 1);
                int   y1 = min(y0 + 1, s - 1);
                float w00 = (1.f - wx) * (1.f - wy), w10 = wx * (1.f - wy);
                float w01 = (1.f - wx) * wy,         w11 = wx * wy;
#pragma unroll
                for (int hf = 0; hf < 2; hf++) {
                    const uint4* base = reinterpret_cast<const uint4*>(g_fm) + (c_loff[lod] << 1) + hf;
                    uint4 t00 = base[(((y0 << sl) + x0) << 1)];
                    uint4 t10 = base[(((y0 << sl) + x1) << 1)];
                    uint4 t01 = base[(((y1 << sl) + x0) << 1)];
                    uint4 t11 = base[(((y1 << sl) + x1) << 1)];
                    const __half2* h00 = reinterpret_cast<const __half2*>(&t00);
                    const __half2* h10 = reinterpret_cast<const __half2*>(&t10);
                    const __half2* h01 = reinterpret_cast<const __half2*>(&t01);
                    const __half2* h11 = reinterpret_cast<const __half2*>(&t11);
                    uint4 res;
                    __half2* ro = reinterpret_cast<__half2*>(&res);
#pragma unroll
                    for (int e = 0; e < 4; e++) {
                        float2 a = __half22float2(h00[e]);
                        float2 b = __half22float2(h10[e]);
                        float2 c = __half22float2(h01[e]);
                        float2 d = __half22float2(h11[e]);
                        float rx = a.x * w00 + b.x * w10 + c.x * w01 + d.x * w11;
                        float ry = a.y * w00 + b.y * w10 + c.y * w01 + d.y * w11;
                        ro[e] = __floats2half2_rn(rx, ry);
                    }
                    *reinterpret_cast<uint4*>(a0 + ptid * A0STRIDE + lod * 16 + hf * 8) = res;
                }
            }
            // signal act0[buf] full
            asm volatile("bar.arrive %0, 384;" :: "r"(2 + buf) : "memory");
        }
    }
}

// =====================================================================
extern "C" void kernel_launch(void* const* d_in, const int* in_sizes, int n_in,
                              void* d_out, int out_size)
{
    const float* xc = (const float*)d_in[0];
    const float* f0 = (const float*)d_in[1];
    const float* f1 = (const float*)d_in[2];
    const float* f2 = (const float*)d_in[3];
    const float* f3 = (const float*)d_in[4];
    const float* f4 = (const float*)d_in[5];
    const float* f5 = (const float*)d_in[6];
    const float* lg = (const float*)d_in[7];
    const float* w0 = (const float*)d_in[8];
    const float* b0 = (const float*)d_in[9];
    const float* w1 = (const float*)d_in[10];
    const float* b1 = (const float*)d_in[11];
    const float* w2 = (const float*)d_in[12];
    const float* b2 = (const float*)d_in[13];
    const float* w3 = (const float*)d_in[14];
    const float* b3 = (const float*)d_in[15];

    int npts   = in_sizes[0] / 2;
    int ntiles = npts / TILE;              // 8192 for 1024x1024

    prep_all<<<(349440 + 46080 + 255) / 256, 256>>>(f0, f1, f2, f3, f4, f5, lg, w0, w1, w2, w3);

    cudaFuncSetAttribute(enc_main, cudaFuncAttributeMaxDynamicSharedMemorySize, SMEM_BYTES);
    int nsm = 0;
    cudaDeviceGetAttribute(&nsm, cudaDevAttrMultiProcessorCount, 0);
    if (nsm <= 0) nsm = 148;

    enc_main<<<nsm, THREADS, SMEM_BYTES>>>(
        (const float2*)xc, b0, b1, b2, b3, (float*)d_out, ntiles);
}